// round 11
// baseline (speedup 1.0000x reference)
#include <cuda_runtime.h>
#include <cuda_fp16.h>
#include <cstdint>

// Batch Conv1D via 1D Winograd F(2,3) on mma.sync (HMMA fp16 in / fp32 acc).
// Round 11: input transform moved to a DRAM-roofline pre-pass (z fp16 global);
// the GEMM is a pure R3-style cp.async pipeline with 2 CTAs/SM.
//   z0=d0-d2, z1=d1+d2, z2=d2-d1, z3=d1-d3   (d_i = x[2t+i], per channel)
//   w0=g0, w1=(g0+g1+g2)/2, w2=(g0-g1+g2)/2, w3=g2
//   y[2t]=m0+m1+m2, y[2t+1]=m1-m2-m3,  m_p = sum_c z_p[c]*w_p[c]
// GEMM CTA: 64 tile-pairs x 64 feats x 4 phases, K=256 in 8 chunks of 32.
// Warps 0-3 accumulate phases {0,1}, warps 4-7 phases {2,3}; combine via smem.

namespace {

constexpr int NTILES = 511;               // output pairs per image
constexpr int ZTILES = 512;               // padded (row 511 zero-init, guarded)
constexpr int NCHUNK = 8;                 // 256 ch / 32
constexpr int NTHREADS = 256;

constexpr int Z_STRIDE = 80;              // 32 fp16 (64B) + 16B pad
constexpr int Z_PHASE  = 64 * Z_STRIDE;   // 5120
constexpr int Z_STAGE  = 4 * Z_PHASE;     // 20480
constexpr int B_STRIDE = 144;             // 64 fp16 (128B) + 16B pad
constexpr int B_PHASE  = 32 * B_STRIDE;   // 4608
constexpr int B_STAGE  = 4 * B_PHASE;     // 18432
constexpr int OFF_B    = 2 * Z_STAGE;     // 40960
constexpr int SMEM_TOTAL = OFF_B + 2 * B_STAGE;   // 77824  -> 2 CTAs/SM

__device__ __half g_wt[4 * 256 * 256];                       // [ph][c][f]
__device__ __half g_z[(size_t)256 * 4 * ZTILES * 256];       // [img][ph][tile][c]

// ---------------- PTX helpers ----------------

__device__ __forceinline__ uint32_t smem_u32(const void* p) {
    return (uint32_t)__cvta_generic_to_shared(p);
}
__device__ __forceinline__ void cp16(uint32_t dst, const void* src) {
    asm volatile("cp.async.cg.shared.global [%0], [%1], 16;" :: "r"(dst), "l"(src));
}
__device__ __forceinline__ void cp_commit() {
    asm volatile("cp.async.commit_group;" ::: "memory");
}
__device__ __forceinline__ void cp_wait1() {
    asm volatile("cp.async.wait_group 1;" ::: "memory");
}
__device__ __forceinline__ void cp_wait0() {
    asm volatile("cp.async.wait_group 0;" ::: "memory");
}
__device__ __forceinline__ void ldsm4(uint32_t (&r)[4], uint32_t addr) {
    asm volatile("ldmatrix.sync.aligned.m8n8.x4.shared.b16 {%0,%1,%2,%3}, [%4];"
                 : "=r"(r[0]), "=r"(r[1]), "=r"(r[2]), "=r"(r[3]) : "r"(addr));
}
__device__ __forceinline__ void ldsm4t(uint32_t (&r)[4], uint32_t addr) {
    asm volatile("ldmatrix.sync.aligned.m8n8.x4.trans.shared.b16 {%0,%1,%2,%3}, [%4];"
                 : "=r"(r[0]), "=r"(r[1]), "=r"(r[2]), "=r"(r[3]) : "r"(addr));
}
__device__ __forceinline__ void mma16816(float (&c)[4], const uint32_t (&a)[4],
                                         uint32_t b0, uint32_t b1) {
    asm volatile(
        "mma.sync.aligned.m16n8k16.row.col.f32.f16.f16.f32 "
        "{%0,%1,%2,%3}, {%4,%5,%6,%7}, {%8,%9}, {%0,%1,%2,%3};"
        : "+f"(c[0]), "+f"(c[1]), "+f"(c[2]), "+f"(c[3])
        : "r"(a[0]), "r"(a[1]), "r"(a[2]), "r"(a[3]), "r"(b0), "r"(b1));
}
__device__ __forceinline__ uint32_t pack_h2(float a, float b) {
    __half2 h = __floats2half2_rn(a, b);
    return *(uint32_t*)&h;
}

// ---------------- pre-pass 1: Winograd weight transform ----------------

__global__ void wgconv_kernel(const float* __restrict__ W) {
    int idx = blockIdx.x * 256 + threadIdx.x;   // 65536 = (c,f)
    float g0 = W[idx];
    float g1 = W[65536 + idx];
    float g2 = W[131072 + idx];
    g_wt[idx]          = __float2half_rn(g0);
    g_wt[65536 + idx]  = __float2half_rn(0.5f * (g0 + g1 + g2));
    g_wt[131072 + idx] = __float2half_rn(0.5f * (g0 - g1 + g2));
    g_wt[196608 + idx] = __float2half_rn(g2);
}

// ---------------- pre-pass 2: input transform x -> z (fp16) ----------------
// grid (64, 256): block = 8 tiles x 32 ch-groups; thread: 1 tile, 8 channels.

__global__ void zconv_kernel(const float* __restrict__ x) {
    const int tid  = threadIdx.x;
    const int tile = blockIdx.x * 8 + (tid >> 5);
    const int img  = blockIdx.y;
    const int ch   = (tid & 31) * 8;
    if (tile >= NTILES) return;

    const float* xr = x + (size_t)img * (1024 * 256) + (size_t)(2 * tile) * 256 + ch;
    float4 d[4][2];
    #pragma unroll
    for (int k = 0; k < 4; ++k) {
        d[k][0] = *(const float4*)(xr + (size_t)k * 256);
        d[k][1] = *(const float4*)(xr + (size_t)k * 256 + 4);
    }

    __half* zb = g_z + (((size_t)img * 4) * ZTILES + tile) * 256 + ch;
    #pragma unroll
    for (int h = 0; h < 2; ++h) {
        const float* d0 = (const float*)&d[0][h];
        const float* d1 = (const float*)&d[1][h];
        const float* d2 = (const float*)&d[2][h];
        const float* d3 = (const float*)&d[3][h];
        uint2 z0, z1, z2, z3;
        z0.x = pack_h2(d0[0] - d2[0], d0[1] - d2[1]);
        z0.y = pack_h2(d0[2] - d2[2], d0[3] - d2[3]);
        z1.x = pack_h2(d1[0] + d2[0], d1[1] + d2[1]);
        z1.y = pack_h2(d1[2] + d2[2], d1[3] + d2[3]);
        z2.x = pack_h2(d2[0] - d1[0], d2[1] - d1[1]);
        z2.y = pack_h2(d2[2] - d1[2], d2[3] - d1[3]);
        z3.x = pack_h2(d1[0] - d3[0], d1[1] - d3[1]);
        z3.y = pack_h2(d1[2] - d3[2], d1[3] - d3[3]);
        *(uint2*)(zb + 0 * (size_t)ZTILES * 256 + h * 4) = z0;
        *(uint2*)(zb + 1 * (size_t)ZTILES * 256 + h * 4) = z1;
        *(uint2*)(zb + 2 * (size_t)ZTILES * 256 + h * 4) = z2;
        *(uint2*)(zb + 3 * (size_t)ZTILES * 256 + h * 4) = z3;
    }
}

// ---------------- main Winograd phase-GEMM ----------------

__global__ __launch_bounds__(NTHREADS, 2)
void conv1d_wino_kernel(const float* __restrict__ bias, float* __restrict__ out)
{
    extern __shared__ __align__(128) uint8_t smem[];
    const uint32_t sm = smem_u32(smem);

    const int tid  = threadIdx.x;
    const int wid  = tid >> 5;
    const int lane = tid & 31;

    const int f0  = blockIdx.x * 64;         // feature tile (4 tiles)
    const int t0  = blockIdx.y * 64;         // tile-pair block (8 blocks)
    const int img = blockIdx.z;

    float* ob = out + (size_t)img * (1022 * 256);

    // warps 0-3: phases {0,1}; warps 4-7: phases {2,3}; 2x2 spatial each
    const int phb = (wid >> 2) * 2;
    const int wq  = wid & 3;
    const int wm  = (wq >> 1) * 32;           // tiles within 64
    const int wn  = (wq & 1) * 32;            // feats within 64

    const uint32_t a_lane = (uint32_t)(wm + (lane & 15)) * Z_STRIDE + (lane >> 4) * 16;
    const uint32_t b_lane = (uint32_t)(lane & 15) * B_STRIDE
                          + (uint32_t)(wn + (lane >> 4) * 8) * 2;

    // ---- staging mappings ----
    // z: 256 rows = 4 phases x 64 tiles; thread = one row (64B = 4 cp16)
    const int zp = tid >> 6;
    const int zr = tid & 63;
    const __half* z_src0 = g_z + (((size_t)img * 4 + zp) * ZTILES + t0 + zr) * 256;
    const uint32_t z_dst = (uint32_t)zp * Z_PHASE + (uint32_t)zr * Z_STRIDE;
    // B: 128 rows = 4 phases x 32 k; 2 threads/row (64B each)
    const int br = tid >> 1, bh = tid & 1;
    const int bp = br >> 5, bk = br & 31;
    const __half* b_src0 = g_wt + ((size_t)bp * 256 + bk) * 256 + f0 + bh * 32;
    const uint32_t b_dst = (uint32_t)bp * B_PHASE + (uint32_t)bk * B_STRIDE + bh * 64;

    auto stage = [&](int s) {
        const int buf = s & 1;
        const __half* zs = z_src0 + s * 32;
        const uint32_t zd = sm + buf * Z_STAGE + z_dst;
        cp16(zd,      zs);
        cp16(zd + 16, zs + 8);
        cp16(zd + 32, zs + 16);
        cp16(zd + 48, zs + 24);
        const __half* bs = b_src0 + (size_t)s * 32 * 256;
        const uint32_t bd = sm + OFF_B + buf * B_STAGE + b_dst;
        cp16(bd,      bs);
        cp16(bd + 16, bs + 8);
        cp16(bd + 32, bs + 16);
        cp16(bd + 48, bs + 24);
        cp_commit();
    };

    float acc[2][2][4][4];
    #pragma unroll
    for (int pp = 0; pp < 2; ++pp)
        #pragma unroll
        for (int mt = 0; mt < 2; ++mt)
            #pragma unroll
            for (int nt = 0; nt < 4; ++nt)
                #pragma unroll
                for (int q = 0; q < 4; ++q)
                    acc[pp][mt][nt][q] = 0.f;

    stage(0);

    for (int s = 0; s < NCHUNK; ++s) {
        if (s + 1 < NCHUNK) { stage(s + 1); cp_wait1(); }
        else                { cp_wait0(); }
        __syncthreads();

        const uint32_t Zb = sm + (s & 1) * Z_STAGE;
        const uint32_t Bb = sm + OFF_B + (s & 1) * B_STAGE;
        #pragma unroll
        for (int pp = 0; pp < 2; ++pp) {
            const int p = phb + pp;
            const uint32_t Ap = Zb + p * Z_PHASE;
            const uint32_t Bp = Bb + p * B_PHASE;
            #pragma unroll
            for (int ks = 0; ks < 2; ++ks) {
                uint32_t af[2][4];
                ldsm4(af[0], Ap + a_lane + ks * 32);
                ldsm4(af[1], Ap + a_lane + 16 * Z_STRIDE + ks * 32);
                uint32_t bf[2][4];
                #pragma unroll
                for (int n2 = 0; n2 < 2; ++n2)
                    ldsm4t(bf[n2], Bp + b_lane + ks * (16 * B_STRIDE) + n2 * 32);
                #pragma unroll
                for (int mt = 0; mt < 2; ++mt)
                    #pragma unroll
                    for (int n2 = 0; n2 < 2; ++n2) {
                        mma16816(acc[pp][mt][2 * n2],     af[mt], bf[n2][0], bf[n2][1]);
                        mma16816(acc[pp][mt][2 * n2 + 1], af[mt], bf[n2][2], bf[n2][3]);
                    }
            }
        }
        __syncthreads();
    }

    // ---- epilogue: warps 4-7 ship m2,m3 via smem; warps 0-3 combine+store ----
    if (wid >= 4) {
        uint8_t* ex = smem + (size_t)(wid - 4) * 8192;
        #pragma unroll
        for (int pp = 0; pp < 2; ++pp)
            #pragma unroll
            for (int mt = 0; mt < 2; ++mt)
                #pragma unroll
                for (int nt = 0; nt < 4; ++nt)
                    *(float4*)(ex + (((pp * 2 + mt) * 4 + nt) * 512) + lane * 16)
                        = *(const float4*)&acc[pp][mt][nt][0];
    }
    __syncthreads();

    if (wid < 4) {
        const uint8_t* ex = smem + (size_t)wq * 8192;
        const int g  = lane >> 2;
        const int tq = lane & 3;
        #pragma unroll
        for (int nt = 0; nt < 4; ++nt) {
            const int col = f0 + wn + nt * 8 + tq * 2;
            const float b0 = __ldg(bias + col);
            const float b1 = __ldg(bias + col + 1);
            #pragma unroll
            for (int mt = 0; mt < 2; ++mt) {
                float4 m2 = *(const float4*)(ex + (((0 * 2 + mt) * 4 + nt) * 512) + lane * 16);
                float4 m3 = *(const float4*)(ex + (((1 * 2 + mt) * 4 + nt) * 512) + lane * 16);
                const float* m0 = acc[0][mt][nt];
                const float* m1 = acc[1][mt][nt];
                const int r = t0 + wm + mt * 16 + g;      // tile-pair index
                if (r < NTILES) {
                    float y00 = m0[0] + m1[0] + m2.x + b0;
                    float y01 = m0[1] + m1[1] + m2.y + b1;
                    float y10 = m1[0] - m2.x - m3.x + b0;
                    float y11 = m1[1] - m2.y - m3.y + b1;
                    *(float2*)(ob + (size_t)(2 * r) * 256 + col)     = make_float2(y00, y01);
                    *(float2*)(ob + (size_t)(2 * r + 1) * 256 + col) = make_float2(y10, y11);
                }
                const int r2 = r + 8;
                if (r2 < NTILES) {
                    float y00 = m0[2] + m1[2] + m2.z + b0;
                    float y01 = m0[3] + m1[3] + m2.w + b1;
                    float y10 = m1[2] - m2.z - m3.z + b0;
                    float y11 = m1[3] - m2.w - m3.w + b1;
                    *(float2*)(ob + (size_t)(2 * r2) * 256 + col)     = make_float2(y00, y01);
                    *(float2*)(ob + (size_t)(2 * r2 + 1) * 256 + col) = make_float2(y10, y11);
                }
            }
        }
    }
}

}  // namespace

extern "C" void kernel_launch(void* const* d_in, const int* in_sizes, int n_in,
                              void* d_out, int out_size)
{
    const float* x  = (const float*)d_in[0];   // [8,32,1024,256]
    const float* w  = (const float*)d_in[1];   // [3,256,256]
    const float* b  = (const float*)d_in[2];   // [256]
    float* out      = (float*)d_out;           // [8,32,1022,256]

    wgconv_kernel<<<256, 256>>>(w);            // Winograd weight transform
    {
        dim3 zg(64, 256);                      // 8 tiles x 32 ch-groups per block
        zconv_kernel<<<zg, 256>>>(x);          // x -> z (fp16), DRAM-roofline
    }

    cudaFuncSetAttribute(conv1d_wino_kernel,
                         cudaFuncAttributeMaxDynamicSharedMemorySize, SMEM_TOTAL);

    dim3 grid(4, 8, 256);                      // f-tiles, tile-blocks, images
    conv1d_wino_kernel<<<grid, NTHREADS, SMEM_TOTAL>>>(b, out);
}

// round 12
// speedup vs baseline: 1.7244x; 1.7244x over previous
#include <cuda_runtime.h>
#include <cuda_fp16.h>
#include <cstdint>

// Batch Conv1D, implicit-im2col GEMM on mma.sync (HMMA fp16 in / fp32 acc).
// Round 12: R3/R5 skeleton (512 MAC/cyc/SM legacy-pipe floor) with the x
// fp32->fp16 conversion fused and CORRECTLY pipelined:
//   - B (fp16 W) staged 2 steps ahead in a 3-slot cp.async ring
//   - A (fp32 x) staged 1 chunk (=3 tap steps) ahead via cp.async
//   - wait_group 1 at step end -> every awaited group was committed >=1 full
//     MMA block earlier (R7's bug was wait_group 0 on the same-step commit)
//   - smem f32 -> smem f16 convert once per chunk on the idle A buffer
// K ordered as (8 channel-chunks x 3 taps); one A tile of 130 rows x 32 ch
// serves all 3 taps (ldmatrix row base shifts by tap). No xconv pre-pass.

namespace {

constexpr int LOUT = 1022;
constexpr int NTHREADS = 256;

constexpr int A_STRIDE = 80;                // 32 fp16 + 16B pad
constexpr int A_BYTES  = 10496;             // 130*80=10400, padded
constexpr int B_STRIDE = 272;               // 128 fp16 + 16B pad
constexpr int B_BYTES  = 8704;              // 32*272
constexpr int F_STRIDE = 144;               // 32 fp32 + 16B pad
constexpr int F_BYTES  = 18816;             // 130*144=18720, padded

constexpr int OFF_A = 0;                    // 2 x A_BYTES   = 20992
constexpr int OFF_B = 2 * A_BYTES;          // 3 x B_BYTES   = 26112 -> 47104
constexpr int OFF_F = OFF_B + 3 * B_BYTES;  // 2 x F_BYTES   = 37632
constexpr int SMEM_TOTAL = OFF_F + 2 * F_BYTES;   // 84736 -> 2 CTAs/SM

__device__ __half g_wf16[768 * 256];

// ---------------- PTX helpers ----------------

__device__ __forceinline__ uint32_t smem_u32(const void* p) {
    return (uint32_t)__cvta_generic_to_shared(p);
}
__device__ __forceinline__ void cp16(uint32_t dst, const void* src) {
    asm volatile("cp.async.cg.shared.global [%0], [%1], 16;" :: "r"(dst), "l"(src));
}
__device__ __forceinline__ void cp_commit() {
    asm volatile("cp.async.commit_group;" ::: "memory");
}
__device__ __forceinline__ void cp_wait1() {
    asm volatile("cp.async.wait_group 1;" ::: "memory");
}
__device__ __forceinline__ void cp_wait0() {
    asm volatile("cp.async.wait_group 0;" ::: "memory");
}
__device__ __forceinline__ void ldsm4(uint32_t (&r)[4], uint32_t addr) {
    asm volatile("ldmatrix.sync.aligned.m8n8.x4.shared.b16 {%0,%1,%2,%3}, [%4];"
                 : "=r"(r[0]), "=r"(r[1]), "=r"(r[2]), "=r"(r[3]) : "r"(addr));
}
__device__ __forceinline__ void ldsm4t(uint32_t (&r)[4], uint32_t addr) {
    asm volatile("ldmatrix.sync.aligned.m8n8.x4.trans.shared.b16 {%0,%1,%2,%3}, [%4];"
                 : "=r"(r[0]), "=r"(r[1]), "=r"(r[2]), "=r"(r[3]) : "r"(addr));
}
__device__ __forceinline__ void mma16816(float (&c)[4], const uint32_t (&a)[4],
                                         uint32_t b0, uint32_t b1) {
    asm volatile(
        "mma.sync.aligned.m16n8k16.row.col.f32.f16.f16.f32 "
        "{%0,%1,%2,%3}, {%4,%5,%6,%7}, {%8,%9}, {%0,%1,%2,%3};"
        : "+f"(c[0]), "+f"(c[1]), "+f"(c[2]), "+f"(c[3])
        : "r"(a[0]), "r"(a[1]), "r"(a[2]), "r"(a[3]), "r"(b0), "r"(b1));
}
__device__ __forceinline__ uint32_t pack_h2(float a, float b) {
    __half2 h = __floats2half2_rn(a, b);
    return *(uint32_t*)&h;
}

// ---------------- pre-pass: W fp32 -> fp16 (tiny) ----------------

__global__ void wconv_kernel(const float* __restrict__ W) {
    int i = blockIdx.x * 256 + threadIdx.x;
    g_wf16[i] = __float2half_rn(W[i]);
}

// ---------------- main GEMM ----------------

__global__ __launch_bounds__(NTHREADS, 2)
void conv1d_hmma_kernel(const float* __restrict__ x,
                        const float* __restrict__ bias,
                        float* __restrict__ out)
{
    extern __shared__ __align__(128) uint8_t smem[];
    const uint32_t sm = smem_u32(smem);

    const int tid  = threadIdx.x;
    const int wid  = tid >> 5;
    const int lane = tid & 31;

    const int f0  = blockIdx.x * 128;
    const int l0  = blockIdx.y * 128;
    const int img = blockIdx.z;

    const float* xb = x   + (size_t)img * (1024 * 256);
    float*       ob = out + (size_t)img * (LOUT * 256);

    // 4x2 warp grid, 32x64 warp tiles (R3 layout)
    const int wm = (wid >> 1) * 32;
    const int wn = (wid & 1) * 64;

    const uint32_t a_lane = (uint32_t)(wm + (lane & 15)) * A_STRIDE + (lane >> 4) * 16;
    const uint32_t b_lane = (uint32_t)(lane & 15) * B_STRIDE
                          + (uint32_t)(wn + (lane >> 4) * 8) * 2;

    // ---- B staging: step s uses k-rows [tap*256 + c*32, +32) of W ----
    const int b_row = tid >> 3;               // 0..31
    const int b_cg  = tid & 7;                // 8 x 16-fp16 groups
    const uint32_t b_dst = (uint32_t)b_row * B_STRIDE + b_cg * 32;

    auto stageB = [&](int s) {
        const int c = s / 3, tap = s - 3 * c;
        const int kr = tap * 256 + c * 32 + b_row;
        const __half* src = g_wf16 + (size_t)kr * 256 + f0 + b_cg * 16;
        const uint32_t d = sm + OFF_B + (s % 3) * B_BYTES + b_dst;
        cp16(d,      src);
        cp16(d + 16, src + 8);
    };

    // ---- A fp32 staging: chunk c = channels [c*32, +32), rows 0..129 ----
    auto stageAF32 = [&](int c) {
        const int buf = c & 1;
        #pragma unroll
        for (int rep = 0; rep < 2; ++rep) {
            const int item = tid + rep * 256;          // 260 half-rows
            if (rep == 0 || tid < 4) {
                const int row = item >> 1, seg = item & 1;
                int xr = l0 + row;
                if (xr > 1023) xr = 1023;              // rows only used for invalid outputs
                const float* src = xb + (size_t)xr * 256 + c * 32 + seg * 16;
                const uint32_t d = sm + OFF_F + buf * F_BYTES
                                 + (uint32_t)row * F_STRIDE + seg * 64;
                cp16(d,      src);
                cp16(d + 16, src + 4);
                cp16(d + 32, src + 8);
                cp16(d + 48, src + 12);
            }
        }
    };

    // ---- convert f32 slot (c&1) -> fp16 A slot (c&1), conflict-free LDS ----
    auto convA = [&](int c) {
        const int buf = c & 1;
        const uint8_t* fb = smem + OFF_F + buf * F_BYTES;
        uint8_t*       ab = smem + OFF_A + buf * A_BYTES;
        #pragma unroll
        for (int rep = 0; rep < 2; ++rep) {
            const int item = tid + rep * 256;
            if (rep == 0 || tid < 4) {
                const int row = item >> 1, seg = item & 1;
                const float* s = (const float*)(fb + (uint32_t)row * F_STRIDE + seg * 64);
                float4 v0 = *(const float4*)(s);
                float4 v1 = *(const float4*)(s + 4);
                float4 v2 = *(const float4*)(s + 8);
                float4 v3 = *(const float4*)(s + 12);
                uint4 u0, u1;
                u0.x = pack_h2(v0.x, v0.y); u0.y = pack_h2(v0.z, v0.w);
                u0.z = pack_h2(v1.x, v1.y); u0.w = pack_h2(v1.z, v1.w);
                u1.x = pack_h2(v2.x, v2.y); u1.y = pack_h2(v2.z, v2.w);
                u1.z = pack_h2(v3.x, v3.y); u1.w = pack_h2(v3.z, v3.w);
                uint8_t* d = ab + (uint32_t)row * A_STRIDE + seg * 32;
                // seg 0 -> bytes [0,32), seg 1 -> [32,64)
                *(uint4*)(d)      = u0;
                *(uint4*)(d + 16) = u1;
            }
        }
    };

    float acc[2][8][4];
    #pragma unroll
    for (int mt = 0; mt < 2; ++mt)
        #pragma unroll
        for (int nt = 0; nt < 8; ++nt)
            #pragma unroll
            for (int q = 0; q < 4; ++q)
                acc[mt][nt][q] = 0.f;

    // ---- prologue: G0={B0}, G1={B1, Af32(0)}; wait all; convert A(0) ----
    stageB(0);
    cp_commit();
    stageB(1);
    stageAF32(0);
    cp_commit();
    cp_wait0();
    __syncthreads();
    convA(0);
    __syncthreads();

    for (int c = 0; c < 8; ++c) {
        #pragma unroll
        for (int tap = 0; tap < 3; ++tap) {
            const int s = c * 3 + tap;

            // stage 2 steps ahead (B) and 1 chunk ahead (A-fp32); one group/step
            if (s + 2 < 24) stageB(s + 2);
            if (tap == 0 && c < 7) stageAF32(c + 1);
            cp_commit();

            // MMA block: A slot (c&1), row base shifted by tap; B slot (s%3)
            const uint32_t sA = sm + OFF_A + (c & 1) * A_BYTES + (uint32_t)tap * A_STRIDE;
            const uint32_t sB = sm + OFF_B + (s % 3) * B_BYTES;
            #pragma unroll
            for (int ks = 0; ks < 2; ++ks) {
                uint32_t af[2][4];
                ldsm4(af[0], sA + a_lane + ks * 32);
                ldsm4(af[1], sA + a_lane + 16 * A_STRIDE + ks * 32);
                uint32_t bf[4][4];
                #pragma unroll
                for (int n2 = 0; n2 < 4; ++n2)
                    ldsm4t(bf[n2], sB + b_lane + ks * (16 * B_STRIDE) + n2 * 32);
                #pragma unroll
                for (int mt = 0; mt < 2; ++mt)
                    #pragma unroll
                    for (int n2 = 0; n2 < 4; ++n2) {
                        mma16816(acc[mt][2 * n2],     af[mt], bf[n2][0], bf[n2][1]);
                        mma16816(acc[mt][2 * n2 + 1], af[mt], bf[n2][2], bf[n2][3]);
                    }
            }

            // convert next chunk's A on the idle buffer (data committed at the
            // tap-0 step of this chunk; wait_group 1 at end of tap-1 covered it)
            if (tap == 2 && c < 7) convA(c + 1);

            if (s < 23) cp_wait1();
            __syncthreads();
        }
    }

    // ---- epilogue: bias + guarded store from registers ----
    const int g  = lane >> 2;
    const int tq = lane & 3;
    #pragma unroll
    for (int nt = 0; nt < 8; ++nt) {
        const int col = f0 + wn + nt * 8 + tq * 2;
        const float b0 = __ldg(bias + col);
        const float b1 = __ldg(bias + col + 1);
        #pragma unroll
        for (int mt = 0; mt < 2; ++mt) {
            const int r = l0 + wm + mt * 16 + g;
            if (r < LOUT) {
                float2 v = make_float2(acc[mt][nt][0] + b0, acc[mt][nt][1] + b1);
                *(float2*)(ob + (size_t)r * 256 + col) = v;
            }
            if (r + 8 < LOUT) {
                float2 v = make_float2(acc[mt][nt][2] + b0, acc[mt][nt][3] + b1);
                *(float2*)(ob + (size_t)(r + 8) * 256 + col) = v;
            }
        }
    }
}

}  // namespace

extern "C" void kernel_launch(void* const* d_in, const int* in_sizes, int n_in,
                              void* d_out, int out_size)
{
    const float* x  = (const float*)d_in[0];   // [8,32,1024,256]
    const float* w  = (const float*)d_in[1];   // [3,256,256]
    const float* b  = (const float*)d_in[2];   // [256]
    float* out      = (float*)d_out;           // [8,32,1022,256]

    wconv_kernel<<<768, 256>>>(w);             // tiny: W fp32 -> fp16

    cudaFuncSetAttribute(conv1d_hmma_kernel,
                         cudaFuncAttributeMaxDynamicSharedMemorySize, SMEM_TOTAL);

    dim3 grid(2, 8, 256);                      // f-tiles, m-tiles, images
    conv1d_hmma_kernel<<<grid, NTHREADS, SMEM_TOTAL>>>(x, b, out);
}